// round 15
// baseline (speedup 1.0000x reference)
#include <cuda_runtime.h>
#include <cuda_fp16.h>
#include <math.h>
#include <stdint.h>

// Problem constants
#define CB 2
#define CT 2048
#define CD 1024
#define CH 16
#define CK 64
#define CDFF 4096
#define CBT (CB*CT)   // 4096 rows

// -------- scratch (device globals; no allocations allowed) --------
__device__ __half g_h1[(size_t)CBT*CD];           // LN1 output (fp16)
__device__ __half g_qkv[3][(size_t)CB*CH*CT*CK];  // q,k,v [B,H,T,K] (fp16)
__device__ __half g_oc[(size_t)CBT*CD];           // attn out concat (fp16)
__device__ float  g_x2[(size_t)CBT*CD];           // residual after attn (fp32)
__device__ __half g_h2[(size_t)CBT*CD];           // LN2 output (fp16)
__device__ __half g_ff[(size_t)CBT*CDFF];         // FF1 activations (fp16)
// transposed weights [N][K] K-major (fp16)
__device__ __half g_qkvwt[(size_t)3*CD*CD];       // 3072 x 1024
__device__ __half g_wot[(size_t)CD*CD];           // 1024 x 1024
__device__ __half g_w1t[(size_t)CDFF*CD];         // 4096 x 1024
__device__ __half g_w2t[(size_t)CD*CDFF];         // 1024 x 4096

// ===================== helpers =======================
__device__ __forceinline__ uint32_t smem_u32(const void* p) {
    uint32_t a;
    asm("{ .reg .u64 t; cvta.to.shared.u64 t, %1; cvt.u32.u64 %0, t; }" : "=r"(a) : "l"(p));
    return a;
}
__device__ __forceinline__ void cp_async16(uint32_t s, const void* g) {
    asm volatile("cp.async.cg.shared.global [%0], [%1], 16;" :: "r"(s), "l"(g));
}
__device__ __forceinline__ void cp_commit() {
    asm volatile("cp.async.commit_group;");
}
// fp16 m16n8k16 mma, fp32 accumulate
__device__ __forceinline__ void mma_f16_16n8k16(float d[4],
                                                const uint32_t a[4],
                                                const uint32_t b[2]) {
    asm volatile(
        "mma.sync.aligned.m16n8k16.row.col.f32.f16.f16.f32 "
        "{%0,%1,%2,%3}, {%4,%5,%6,%7}, {%8,%9}, {%0,%1,%2,%3};\n"
        : "+f"(d[0]), "+f"(d[1]), "+f"(d[2]), "+f"(d[3])
        : "r"(a[0]), "r"(a[1]), "r"(a[2]), "r"(a[3]), "r"(b[0]), "r"(b[1]));
}
#define LDSM4(r0, r1, r2, r3, addr) \
    asm volatile("ldmatrix.sync.aligned.m8n8.x4.shared.b16 {%0,%1,%2,%3}, [%4];" \
        : "=r"(r0), "=r"(r1), "=r"(r2), "=r"(r3) : "r"(addr))
#define LDSM4T(r0, r1, r2, r3, addr) \
    asm volatile("ldmatrix.sync.aligned.m8n8.x4.trans.shared.b16 {%0,%1,%2,%3}, [%4];" \
        : "=r"(r0), "=r"(r1), "=r"(r2), "=r"(r3) : "r"(addr))

// ===================== transposes (weights -> [N][K], fp16) ========
__device__ __forceinline__ void tr_body(const float* __restrict__ src,
                                        __half* __restrict__ dst, int R, int C) {
    __shared__ float t[32][33];
    int c0 = blockIdx.x * 32, r0 = blockIdx.y * 32;
    int x = threadIdx.x, y = threadIdx.y;
#pragma unroll
    for (int i = 0; i < 32; i += 8) t[y + i][x] = src[(size_t)(r0 + y + i) * C + c0 + x];
    __syncthreads();
#pragma unroll
    for (int i = 0; i < 32; i += 8)
        dst[(size_t)(c0 + y + i) * R + r0 + x] = __float2half_rn(t[x][y + i]);
}
__global__ void k_tr(const float* __restrict__ src, __half* __restrict__ dst, int R, int C) {
    tr_body(src, dst, R, C);
}
__global__ void k_qkvw_tr(const float* __restrict__ Wq, const float* __restrict__ Wk,
                          const float* __restrict__ Wv) {
    int zh = blockIdx.z;
    const float* base = (zh < 16) ? Wq : (zh < 32) ? Wk : Wv;
    const float* src = base + (size_t)(zh & 15) * CD * CK;   // [1024][64]
    __half* dst = g_qkvwt + (size_t)zh * CK * CD;            // [64][1024]
    tr_body(src, dst, CD, CK);
}

// ============================ LayerNorm ============================
__device__ __forceinline__ void ln_body(const float* __restrict__ in,
                                        const float* __restrict__ g,
                                        const float* __restrict__ be,
                                        __half* __restrict__ out) {
    int row = blockIdx.x;
    int tid = threadIdx.x;
    const float* xr = in + (size_t)row * CD;
    float v[4];
    float s = 0.f;
#pragma unroll
    for (int i = 0; i < 4; i++) { v[i] = xr[tid + i*256]; s += v[i]; }

    __shared__ float red[8];
#pragma unroll
    for (int o = 16; o; o >>= 1) s += __shfl_xor_sync(0xffffffffu, s, o);
    if ((tid & 31) == 0) red[tid >> 5] = s;
    __syncthreads();
    float tot = 0.f;
#pragma unroll
    for (int i = 0; i < 8; i++) tot += red[i];
    float mu = tot * (1.f / CD);

    float s2 = 0.f;
#pragma unroll
    for (int i = 0; i < 4; i++) { float d = v[i] - mu; s2 += d * d; }
    __syncthreads();
#pragma unroll
    for (int o = 16; o; o >>= 1) s2 += __shfl_xor_sync(0xffffffffu, s2, o);
    if ((tid & 31) == 0) red[tid >> 5] = s2;
    __syncthreads();
    float tot2 = 0.f;
#pragma unroll
    for (int i = 0; i < 8; i++) tot2 += red[i];
    float rstd = rsqrtf(tot2 * (1.f / CD) + 1e-5f);

    __half* orow = out + (size_t)row * CD;
#pragma unroll
    for (int i = 0; i < 4; i++) {
        int c = tid + i*256;
        orow[c] = __float2half_rn((v[i] - mu) * rstd * g[c] + be[c]);
    }
}
__global__ void k_ln1(const float* __restrict__ x, const float* __restrict__ g,
                      const float* __restrict__ be) { ln_body(x, g, be, g_h1); }
__global__ void k_ln2(const float* __restrict__ g, const float* __restrict__ be) {
    ln_body(g_x2, g, be, g_h2);
}

// ===================== fp16 mma.sync GEMM ==========================
// C[128 x 128] tile per CTA, 256 thr / 8 warps (2M x 4N), warp 64x32 via
// 4x4 m16n8k16. K chunks of 64 halves, 2-stage cp.async pipeline with a
// SINGLE __syncthreads per chunk (wait -> bar -> prefetch -> compute).
// MODE: 0=QKV scatter(fp16), 1=Wo(+x+bo), 2=FF1(+b1,gelu->fp16), 3=FF2(+res+b2)
#define KCH 64
#define SROW 36                          // words per row (72 halves)
#define STG_W (128 * SROW)
#define GEMM_SMEM (4 * STG_W * 4)

template<int MODE>
__global__ void __launch_bounds__(256, 2) k_gemm(
    const __half* __restrict__ A, int lda,
    const __half* __restrict__ Bt, int kdim,
    const float* __restrict__ bias,
    const float* __restrict__ xres,
    float* __restrict__ out, int ldout)
{
    extern __shared__ uint32_t smw[];

    int tid = threadIdx.x, wid = tid >> 5, lane = tid & 31;
    int m0 = blockIdx.x * 128, n0 = blockIdx.y * 128;
    int wm = (wid >> 2) * 64, wn = (wid & 3) * 32;
    int gid = lane >> 2, tig = lane & 3;

    float acc[4][4][4];
#pragma unroll
    for (int i = 0; i < 4; i++)
#pragma unroll
        for (int j = 0; j < 4; j++)
#pragma unroll
            for (int q = 0; q < 4; q++) acc[i][j][q] = 0.f;

    uint32_t sb = smem_u32(smw);
    const int nch = kdim >> 6;

    // ldmatrix per-lane offsets (bytes, within stage)
    int l8 = lane & 7, b3 = (lane >> 3) & 1, b4 = lane >> 4;
    uint32_t aoff[4];
#pragma unroll
    for (int mt = 0; mt < 4; mt++)
        aoff[mt] = (uint32_t)((wm + 16 * mt + l8 + 8 * b3) * SROW) * 4 + 16u * b4;
    uint32_t boff[2];
#pragma unroll
    for (int j = 0; j < 2; j++)
        boff[j] = (uint32_t)((wn + 8 * (2 * j + b4) + l8) * SROW) * 4 + 16u * b3;

    // loader lane mapping
    int lrow = tid >> 3, lqc = tid & 7;

    // prefetch chunk 0 -> stage 0
#pragma unroll
    for (int i = 0; i < 4; i++) {
        int row = lrow + i * 32;
        uint32_t soff = (uint32_t)(row * SROW + lqc * 4) * 4;
        cp_async16(sb + soff, A + (size_t)(m0 + row) * lda + lqc * 8);
        cp_async16(sb + (uint32_t)(2 * STG_W) * 4 + soff,
                   Bt + (size_t)(n0 + row) * kdim + lqc * 8);
    }
    cp_commit();

    for (int c = 0; c < nch; c++) {
        asm volatile("cp.async.wait_group 0;");
        __syncthreads();
        if (c + 1 < nch) {
            int pn = (c + 1) & 1;
            uint32_t asn = sb + (uint32_t)(pn * STG_W) * 4;
            uint32_t bsn = asn + (uint32_t)(2 * STG_W) * 4;
            const __half* An = A + (c + 1) * KCH;
            const __half* Bn = Bt + (c + 1) * KCH;
#pragma unroll
            for (int i = 0; i < 4; i++) {
                int row = lrow + i * 32;
                uint32_t soff = (uint32_t)(row * SROW + lqc * 4) * 4;
                cp_async16(asn + soff, An + (size_t)(m0 + row) * lda + lqc * 8);
                cp_async16(bsn + soff, Bn + (size_t)(n0 + row) * kdim + lqc * 8);
            }
            cp_commit();
        }

        int p = c & 1;
        uint32_t abase = sb + (uint32_t)(p * STG_W) * 4;
        uint32_t bbase = abase + (uint32_t)(2 * STG_W) * 4;
#pragma unroll
        for (int kk = 0; kk < 4; kk++) {
            uint32_t kadd = (uint32_t)(kk * 32);
            uint32_t a[4][4], b[4][2];
#pragma unroll
            for (int mt = 0; mt < 4; mt++)
                LDSM4(a[mt][0], a[mt][1], a[mt][2], a[mt][3], abase + aoff[mt] + kadd);
            LDSM4(b[0][0], b[0][1], b[1][0], b[1][1], bbase + boff[0] + kadd);
            LDSM4(b[2][0], b[2][1], b[3][0], b[3][1], bbase + boff[1] + kadd);
#pragma unroll
            for (int mt = 0; mt < 4; mt++)
#pragma unroll
                for (int nt = 0; nt < 4; nt++)
                    mma_f16_16n8k16(acc[mt][nt], a[mt], b[nt]);
        }
    }

    // fused epilogue
#pragma unroll
    for (int mt = 0; mt < 4; mt++) {
#pragma unroll
        for (int half_ = 0; half_ < 2; half_++) {
            int grow = m0 + wm + 16 * mt + gid + 8 * half_;
#pragma unroll
            for (int nt = 0; nt < 4; nt++) {
                int gcol = n0 + wn + 8 * nt + 2 * tig;
                float v0 = acc[mt][nt][half_ * 2 + 0];
                float v1 = acc[mt][nt][half_ * 2 + 1];
                if (MODE == 0) {
                    int z = gcol >> 10, rem = gcol & 1023, h = rem >> 6, kk = rem & 63;
                    int b = grow >> 11, t = grow & 2047;
                    __half* dst = &g_qkv[z][(((size_t)(b * CH + h) * CT) + t) * CK + kk];
                    *(__half2*)dst = __floats2half2_rn(v0, v1);
                } else if (MODE == 1 || MODE == 3) {
                    const float* xr = &xres[(size_t)grow * ldout + gcol];
                    float* dst = &out[(size_t)grow * ldout + gcol];
                    dst[0] = xr[0] + v0 + bias[gcol];
                    dst[1] = xr[1] + v1 + bias[gcol + 1];
                } else {
                    float u0 = v0 + bias[gcol];
                    float u1 = v1 + bias[gcol + 1];
                    float r0 = 0.5f * u0 * (1.f + erff(u0 * 0.70710678118654752f));
                    float r1 = 0.5f * u1 * (1.f + erff(u1 * 0.70710678118654752f));
                    __half* oh = (__half*)out;
                    *(__half2*)&oh[(size_t)grow * ldout + gcol] =
                        __floats2half2_rn(r0, r1);
                }
            }
        }
    }
}

// ================ Flash attention on mma.sync fp16 =================
// CTA: 64 queries x one (b,h). 128 threads / 4 warps; warp owns 16 rows.
// K and V double-buffered via cp.async (natural [key][d], row 72 halves).
// PV B-operand read from natural V via ldmatrix.trans.
// smem: K[2], V[2] stages + Ps (Q staging, then P tiles).
#define AROW 72                              // halves per row
#define RB 144                               // bytes per row
#define KVB (64 * RB)                        // bytes per stage = 9216
#define ATTN_SMEM_BYTES (5 * KVB)            // K0,K1,V0,V1,Ps = 46080

__global__ void __launch_bounds__(128) k_attn_mma() {
    extern __shared__ __half smh[];
    __half* Psh = smh + 4 * (KVB / 2);

    int tid = threadIdx.x, wid = tid >> 5, lane = tid & 31;
    int gid = lane >> 2, tig = lane & 3;
    int qi = blockIdx.x, bh = blockIdx.y;
    int q0 = qi * 64;

    uint32_t sb  = smem_u32(smh);
    uint32_t ksb = sb;                 // stages 0,1
    uint32_t vsb = sb + 2 * KVB;       // stages 0,1
    uint32_t psb = sb + 4 * KVB;

    const __half* Q  = g_qkv[0] + (size_t)bh * CT * CK;
    const __half* Kp = g_qkv[1] + (size_t)bh * CT * CK;
    const __half* Vp = g_qkv[2] + (size_t)bh * CT * CK;

    // ldmatrix per-lane offsets
    int l8 = lane & 7, b3 = (lane >> 3) & 1, b4 = lane >> 4;
    uint32_t aoffP = (uint32_t)((wid * 16 + l8 + 8 * b3) * RB) + 16u * b4;
    uint32_t boffK[4];
#pragma unroll
    for (int j = 0; j < 4; j++)
        boffK[j] = (uint32_t)((8 * (2 * j + b4) + l8) * RB) + 16u * b3;
    // V trans: rows = key (khalf via b3), 16B col = d-block (2j + b4)
    uint32_t boffV[4];
#pragma unroll
    for (int j = 0; j < 4; j++)
        boffV[j] = (uint32_t)((8 * b3 + l8) * RB) + (uint32_t)(2 * j + b4) * 16u;

    int lrow = tid >> 3, lqc = tid & 7;    // loader mapping (2 rows per i-iter)

    // stage Q (scaled by 1/8) into Ps
    const __half2 qscale = __float2half2_rn(0.125f);
#pragma unroll
    for (int i = 0; i < 4; i++) {
        int idx = tid + i * 128;
        int r = idx >> 3, qc = idx & 7;
        uint4 v = *(const uint4*)(Q + (size_t)(q0 + r) * CK + qc * 8);
        __half2* h = (__half2*)&v;
        h[0] = __hmul2(h[0], qscale); h[1] = __hmul2(h[1], qscale);
        h[2] = __hmul2(h[2], qscale); h[3] = __hmul2(h[3], qscale);
        *(uint4*)&Psh[r * AROW + qc * 8] = v;
    }
    __syncthreads();

    int rA = wid * 16 + gid;           // warp row A; row B = rA + 8
    uint32_t qf[4][4];
#pragma unroll
    for (int kk = 0; kk < 4; kk++)
        LDSM4(qf[kk][0], qf[kk][1], qf[kk][2], qf[kk][3],
              psb + aoffP + (uint32_t)(kk * 32));

    float oacc[8][4];
#pragma unroll
    for (int nt = 0; nt < 8; nt++)
#pragma unroll
        for (int q = 0; q < 4; q++) oacc[nt][q] = 0.f;
    float mA = -INFINITY, mB = -INFINITY, lA = 0.f, lB = 0.f;

    int grA = q0 + rA, grB = grA + 8;
    const int nkb = qi + 1;

    // prefetch kb=0 -> stage 0
#pragma unroll
    for (int i = 0; i < 4; i++) {
        int row = lrow + i * 16;
        uint32_t soff = (uint32_t)(row * RB) + (uint32_t)(lqc * 16);
        cp_async16(ksb + soff, Kp + (size_t)row * CK + lqc * 8);
        cp_async16(vsb + soff, Vp + (size_t)row * CK + lqc * 8);
    }
    cp_commit();

    for (int kb = 0; kb < nkb; kb++) {
        asm volatile("cp.async.wait_group 0;");
        __syncthreads();
        if (kb + 1 < nkb) {
            uint32_t stoff = (uint32_t)(((kb + 1) & 1) * KVB);
            const __half* Kn = Kp + (size_t)(kb + 1) * 64 * CK;
            const __half* Vn = Vp + (size_t)(kb + 1) * 64 * CK;
#pragma unroll
            for (int i = 0; i < 4; i++) {
                int row = lrow + i * 16;
                uint32_t soff = stoff + (uint32_t)(row * RB) + (uint32_t)(lqc * 16);
                cp_async16(ksb + soff, Kn + (size_t)row * CK + lqc * 8);
                cp_async16(vsb + soff, Vn + (size_t)row * CK + lqc * 8);
            }
            cp_commit();
        }
        uint32_t st = (uint32_t)((kb & 1) * KVB);

        // S = Q K^T  (warp: 16 x 64)
        float sacc[8][4];
#pragma unroll
        for (int nt = 0; nt < 8; nt++)
#pragma unroll
            for (int q = 0; q < 4; q++) sacc[nt][q] = 0.f;
#pragma unroll
        for (int kk = 0; kk < 4; kk++) {
            uint32_t kadd = (uint32_t)(kk * 32);
#pragma unroll
            for (int j = 0; j < 4; j++) {
                uint32_t bb[4];
                LDSM4(bb[0], bb[1], bb[2], bb[3], ksb + st + boffK[j] + kadd);
                mma_f16_16n8k16(sacc[2 * j], qf[kk], bb);
                mma_f16_16n8k16(sacc[2 * j + 1], qf[kk], bb + 2);
            }
        }

        // causal mask (register)
        if (kb * 64 + 63 > q0 + wid * 16) {
#pragma unroll
            for (int nt = 0; nt < 8; nt++) {
                int c0 = kb * 64 + 8 * nt + 2 * tig;
                if (c0     > grA) sacc[nt][0] = -INFINITY;
                if (c0 + 1 > grA) sacc[nt][1] = -INFINITY;
                if (c0     > grB) sacc[nt][2] = -INFINITY;
                if (c0 + 1 > grB) sacc[nt][3] = -INFINITY;
            }
        }

        // online softmax (fp32 registers)
        float mxA = -INFINITY, mxB = -INFINITY;
#pragma unroll
        for (int nt = 0; nt < 8; nt++) {
            mxA = fmaxf(mxA, fmaxf(sacc[nt][0], sacc[nt][1]));
            mxB = fmaxf(mxB, fmaxf(sacc[nt][2], sacc[nt][3]));
        }
        mxA = fmaxf(mxA, __shfl_xor_sync(0xffffffffu, mxA, 1));
        mxA = fmaxf(mxA, __shfl_xor_sync(0xffffffffu, mxA, 2));
        mxB = fmaxf(mxB, __shfl_xor_sync(0xffffffffu, mxB, 1));
        mxB = fmaxf(mxB, __shfl_xor_sync(0xffffffffu, mxB, 2));
        float mnA = fmaxf(mA, mxA), mnB = fmaxf(mB, mxB);
        float aA = __expf(mA - mnA), aB = __expf(mB - mnB);
        lA *= aA; lB *= aB;
        __half* prA = &Psh[rA * AROW];
        __half* prB = prA + 8 * AROW;
#pragma unroll
        for (int nt = 0; nt < 8; nt++) {
            float p0 = __expf(sacc[nt][0] - mnA);
            float p1 = __expf(sacc[nt][1] - mnA);
            float p2 = __expf(sacc[nt][2] - mnB);
            float p3 = __expf(sacc[nt][3] - mnB);
            lA += p0 + p1; lB += p2 + p3;
            int c = 8 * nt + 2 * tig;
            *(__half2*)&prA[c] = __floats2half2_rn(p0, p1);
            *(__half2*)&prB[c] = __floats2half2_rn(p2, p3);
            oacc[nt][0] *= aA; oacc[nt][1] *= aA;
            oacc[nt][2] *= aB; oacc[nt][3] *= aB;
        }
        mA = mnA; mB = mnB;
        __syncwarp();

        // O += P V  (A = own-warp P rows via LDSM, B = natural V via LDSM.trans)
#pragma unroll
        for (int kk = 0; kk < 4; kk++) {
            uint32_t pa[4];
            LDSM4(pa[0], pa[1], pa[2], pa[3], psb + aoffP + (uint32_t)(kk * 32));
            uint32_t vkadd = (uint32_t)(kk * 16 * RB);   // advance 16 keys
#pragma unroll
            for (int j = 0; j < 4; j++) {
                uint32_t bb[4];
                LDSM4T(bb[0], bb[1], bb[2], bb[3], vsb + st + boffV[j] + vkadd);
                mma_f16_16n8k16(oacc[2 * j], pa, bb);
                mma_f16_16n8k16(oacc[2 * j + 1], pa, bb + 2);
            }
        }
        __syncwarp();
    }

    lA += __shfl_xor_sync(0xffffffffu, lA, 1);
    lA += __shfl_xor_sync(0xffffffffu, lA, 2);
    lB += __shfl_xor_sync(0xffffffffu, lB, 1);
    lB += __shfl_xor_sync(0xffffffffu, lB, 2);
    float iA = 1.f / lA, iB = 1.f / lB;

    // write concat output (fp16, feeds Wo GEMM as A operand)
    int b = bh >> 4, h = bh & 15;
    size_t baseA = ((size_t)(b * CT + grA)) * CD + h * 64;
    size_t baseB = ((size_t)(b * CT + grB)) * CD + h * 64;
#pragma unroll
    for (int nt = 0; nt < 8; nt++) {
        int c = 8 * nt + 2 * tig;
        *(__half2*)&g_oc[baseA + c] = __floats2half2_rn(oacc[nt][0] * iA, oacc[nt][1] * iA);
        *(__half2*)&g_oc[baseB + c] = __floats2half2_rn(oacc[nt][2] * iB, oacc[nt][3] * iB);
    }
}

// ============================= launch ==============================
extern "C" void kernel_launch(void* const* d_in, const int* in_sizes, int n_in,
                              void* d_out, int out_size) {
    (void)in_sizes; (void)n_in; (void)out_size;
    const float* x   = (const float*)d_in[0];
    const float* Wq  = (const float*)d_in[1];
    const float* Wk  = (const float*)d_in[2];
    const float* Wv  = (const float*)d_in[3];
    const float* Wo  = (const float*)d_in[4];
    const float* bo  = (const float*)d_in[5];
    const float* W1  = (const float*)d_in[6];
    const float* b1  = (const float*)d_in[7];
    const float* W2  = (const float*)d_in[8];
    const float* b2  = (const float*)d_in[9];
    const float* g1  = (const float*)d_in[10];
    const float* be1 = (const float*)d_in[11];
    const float* g2  = (const float*)d_in[12];
    const float* be2 = (const float*)d_in[13];
    float* out = (float*)d_out;

    cudaFuncSetAttribute(k_attn_mma, cudaFuncAttributeMaxDynamicSharedMemorySize, ATTN_SMEM_BYTES);
    cudaFuncSetAttribute(k_gemm<0>, cudaFuncAttributeMaxDynamicSharedMemorySize, GEMM_SMEM);
    cudaFuncSetAttribute(k_gemm<1>, cudaFuncAttributeMaxDynamicSharedMemorySize, GEMM_SMEM);
    cudaFuncSetAttribute(k_gemm<2>, cudaFuncAttributeMaxDynamicSharedMemorySize, GEMM_SMEM);
    cudaFuncSetAttribute(k_gemm<3>, cudaFuncAttributeMaxDynamicSharedMemorySize, GEMM_SMEM);

    __half* g_qkvwt_p; cudaGetSymbolAddress((void**)&g_qkvwt_p, g_qkvwt);
    __half* g_wot_p;   cudaGetSymbolAddress((void**)&g_wot_p, g_wot);
    __half* g_w1t_p;   cudaGetSymbolAddress((void**)&g_w1t_p, g_w1t);
    __half* g_w2t_p;   cudaGetSymbolAddress((void**)&g_w2t_p, g_w2t);
    __half* g_h1_p;    cudaGetSymbolAddress((void**)&g_h1_p, g_h1);
    __half* g_oc_p;    cudaGetSymbolAddress((void**)&g_oc_p, g_oc);
    float*  g_x2_p;    cudaGetSymbolAddress((void**)&g_x2_p, g_x2);
    __half* g_h2_p;    cudaGetSymbolAddress((void**)&g_h2_p, g_h2);
    __half* g_ff_p;    cudaGetSymbolAddress((void**)&g_ff_p, g_ff);

    // weight transposes -> [N][K] fp16
    k_qkvw_tr<<<dim3(CK / 32, CD / 32, 48), dim3(32, 8)>>>(Wq, Wk, Wv);
    k_tr<<<dim3(CD / 32, CD / 32), dim3(32, 8)>>>(Wo, g_wot_p, CD, CD);
    k_tr<<<dim3(CDFF / 32, CD / 32), dim3(32, 8)>>>(W1, g_w1t_p, CD, CDFF);
    k_tr<<<dim3(CD / 32, CDFF / 32), dim3(32, 8)>>>(W2, g_w2t_p, CDFF, CD);

    k_ln1<<<CBT, 256>>>(x, g1, be1);
    // QKV: [4096 x 3072]
    k_gemm<0><<<dim3(CBT / 128, 3 * CD / 128), 256, GEMM_SMEM>>>(
        g_h1_p, CD, g_qkvwt_p, CD, nullptr, nullptr, nullptr, 0);
    k_attn_mma<<<dim3(CT / 64, CB * CH), 128, ATTN_SMEM_BYTES>>>();
    // Wo + residual
    k_gemm<1><<<dim3(CBT / 128, CD / 128), 256, GEMM_SMEM>>>(
        g_oc_p, CD, g_wot_p, CD, bo, x, g_x2_p, CD);
    k_ln2<<<CBT, 256>>>(g2, be2);
    // FF1 + gelu -> fp16 g_ff
    k_gemm<2><<<dim3(CBT / 128, CDFF / 128), 256, GEMM_SMEM>>>(
        g_h2_p, CD, g_w1t_p, CD, b1, nullptr, (float*)g_ff_p, CDFF);
    // FF2 + residual -> out
    k_gemm<3><<<dim3(CBT / 128, CD / 128), 256, GEMM_SMEM>>>(
        g_ff_p, CDFF, g_w2t_p, CDFF, b2, g_x2_p, out, CD);
}

// round 17
// speedup vs baseline: 1.4940x; 1.4940x over previous
#include <cuda_runtime.h>
#include <cuda_fp16.h>
#include <math.h>
#include <stdint.h>

// Problem constants
#define CB 2
#define CT 2048
#define CD 1024
#define CH 16
#define CK 64
#define CDFF 4096
#define CBT (CB*CT)   // 4096 rows

// -------- scratch (device globals; no allocations allowed) --------
__device__ __half g_h1[(size_t)CBT*CD];           // LN1 output (fp16)
__device__ __half g_qkv[3][(size_t)CB*CH*CT*CK];  // q,k,v [B,H,T,K] (fp16)
__device__ __half g_oc[(size_t)CBT*CD];           // attn out concat (fp16)
__device__ float  g_x2[(size_t)CBT*CD];           // residual after attn (fp32)
__device__ __half g_h2[(size_t)CBT*CD];           // LN2 output (fp16)
__device__ __half g_ff[(size_t)CBT*CDFF];         // FF1 activations (fp16)
// transposed weights [N][K] K-major (fp16)
__device__ __half g_qkvwt[(size_t)3*CD*CD];       // 3072 x 1024
__device__ __half g_wot[(size_t)CD*CD];           // 1024 x 1024
__device__ __half g_w1t[(size_t)CDFF*CD];         // 4096 x 1024
__device__ __half g_w2t[(size_t)CD*CDFF];         // 1024 x 4096

// ===================== helpers =======================
__device__ __forceinline__ uint32_t smem_u32(const void* p) {
    uint32_t a;
    asm("{ .reg .u64 t; cvta.to.shared.u64 t, %1; cvt.u32.u64 %0, t; }" : "=r"(a) : "l"(p));
    return a;
}
__device__ __forceinline__ void cp_async16(uint32_t s, const void* g) {
    asm volatile("cp.async.cg.shared.global [%0], [%1], 16;" :: "r"(s), "l"(g));
}
__device__ __forceinline__ void cp_commit() {
    asm volatile("cp.async.commit_group;");
}
// fp16 m16n8k16 mma, fp32 accumulate
__device__ __forceinline__ void mma_f16_16n8k16(float d[4],
                                                const uint32_t a[4],
                                                const uint32_t b[2]) {
    asm volatile(
        "mma.sync.aligned.m16n8k16.row.col.f32.f16.f16.f32 "
        "{%0,%1,%2,%3}, {%4,%5,%6,%7}, {%8,%9}, {%0,%1,%2,%3};\n"
        : "+f"(d[0]), "+f"(d[1]), "+f"(d[2]), "+f"(d[3])
        : "r"(a[0]), "r"(a[1]), "r"(a[2]), "r"(a[3]), "r"(b[0]), "r"(b[1]));
}
#define LDSM4(r0, r1, r2, r3, addr) \
    asm volatile("ldmatrix.sync.aligned.m8n8.x4.shared.b16 {%0,%1,%2,%3}, [%4];" \
        : "=r"(r0), "=r"(r1), "=r"(r2), "=r"(r3) : "r"(addr))
#define LDSM4T(r0, r1, r2, r3, addr) \
    asm volatile("ldmatrix.sync.aligned.m8n8.x4.trans.shared.b16 {%0,%1,%2,%3}, [%4];" \
        : "=r"(r0), "=r"(r1), "=r"(r2), "=r"(r3) : "r"(addr))

// ===================== transposes (weights -> [N][K], fp16) ========
__device__ __forceinline__ void tr_body(const float* __restrict__ src,
                                        __half* __restrict__ dst, int R, int C) {
    __shared__ float t[32][33];
    int c0 = blockIdx.x * 32, r0 = blockIdx.y * 32;
    int x = threadIdx.x, y = threadIdx.y;
#pragma unroll
    for (int i = 0; i < 32; i += 8) t[y + i][x] = src[(size_t)(r0 + y + i) * C + c0 + x];
    __syncthreads();
#pragma unroll
    for (int i = 0; i < 32; i += 8)
        dst[(size_t)(c0 + y + i) * R + r0 + x] = __float2half_rn(t[x][y + i]);
}
__global__ void k_tr(const float* __restrict__ src, __half* __restrict__ dst, int R, int C) {
    tr_body(src, dst, R, C);
}
__global__ void k_qkvw_tr(const float* __restrict__ Wq, const float* __restrict__ Wk,
                          const float* __restrict__ Wv) {
    int zh = blockIdx.z;
    const float* base = (zh < 16) ? Wq : (zh < 32) ? Wk : Wv;
    const float* src = base + (size_t)(zh & 15) * CD * CK;   // [1024][64]
    __half* dst = g_qkvwt + (size_t)zh * CK * CD;            // [64][1024]
    tr_body(src, dst, CD, CK);
}

// ============================ LayerNorm ============================
__device__ __forceinline__ void ln_body(const float* __restrict__ in,
                                        const float* __restrict__ g,
                                        const float* __restrict__ be,
                                        __half* __restrict__ out) {
    int row = blockIdx.x;
    int tid = threadIdx.x;
    const float* xr = in + (size_t)row * CD;
    float v[4];
    float s = 0.f;
#pragma unroll
    for (int i = 0; i < 4; i++) { v[i] = xr[tid + i*256]; s += v[i]; }

    __shared__ float red[8];
#pragma unroll
    for (int o = 16; o; o >>= 1) s += __shfl_xor_sync(0xffffffffu, s, o);
    if ((tid & 31) == 0) red[tid >> 5] = s;
    __syncthreads();
    float tot = 0.f;
#pragma unroll
    for (int i = 0; i < 8; i++) tot += red[i];
    float mu = tot * (1.f / CD);

    float s2 = 0.f;
#pragma unroll
    for (int i = 0; i < 4; i++) { float d = v[i] - mu; s2 += d * d; }
    __syncthreads();
#pragma unroll
    for (int o = 16; o; o >>= 1) s2 += __shfl_xor_sync(0xffffffffu, s2, o);
    if ((tid & 31) == 0) red[tid >> 5] = s2;
    __syncthreads();
    float tot2 = 0.f;
#pragma unroll
    for (int i = 0; i < 8; i++) tot2 += red[i];
    float rstd = rsqrtf(tot2 * (1.f / CD) + 1e-5f);

    __half* orow = out + (size_t)row * CD;
#pragma unroll
    for (int i = 0; i < 4; i++) {
        int c = tid + i*256;
        orow[c] = __float2half_rn((v[i] - mu) * rstd * g[c] + be[c]);
    }
}
__global__ void k_ln1(const float* __restrict__ x, const float* __restrict__ g,
                      const float* __restrict__ be) { ln_body(x, g, be, g_h1); }
__global__ void k_ln2(const float* __restrict__ g, const float* __restrict__ be) {
    ln_body(g_x2, g, be, g_h2);
}

// ===================== fp16 mma.sync GEMM ==========================
// (identical to R14 — best measured config)
#define KCH 64
#define SROW 36                          // words per row (72 halves)
#define STG_W (128 * SROW)
#define GEMM_SMEM (4 * STG_W * 4)

template<int MODE>
__global__ void __launch_bounds__(256, 2) k_gemm(
    const __half* __restrict__ A, int lda,
    const __half* __restrict__ Bt, int kdim,
    const float* __restrict__ bias,
    const float* __restrict__ xres,
    float* __restrict__ out, int ldout)
{
    extern __shared__ uint32_t smw[];

    int tid = threadIdx.x, wid = tid >> 5, lane = tid & 31;
    int m0 = blockIdx.x * 128, n0 = blockIdx.y * 128;
    int wm = (wid >> 2) * 64, wn = (wid & 3) * 32;
    int gid = lane >> 2, tig = lane & 3;

    float acc[4][4][4];
#pragma unroll
    for (int i = 0; i < 4; i++)
#pragma unroll
        for (int j = 0; j < 4; j++)
#pragma unroll
            for (int q = 0; q < 4; q++) acc[i][j][q] = 0.f;

    uint32_t sb = smem_u32(smw);
    const int nch = kdim >> 6;

    // ldmatrix per-lane offsets (bytes, within stage)
    int l8 = lane & 7, b3 = (lane >> 3) & 1, b4 = lane >> 4;
    uint32_t aoff[4];
#pragma unroll
    for (int mt = 0; mt < 4; mt++)
        aoff[mt] = (uint32_t)((wm + 16 * mt + l8 + 8 * b3) * SROW) * 4 + 16u * b4;
    uint32_t boff[2];
#pragma unroll
    for (int j = 0; j < 2; j++)
        boff[j] = (uint32_t)((wn + 8 * (2 * j + b4) + l8) * SROW) * 4 + 16u * b3;

#pragma unroll
    for (int i = 0; i < 4; i++) {
        int idx = tid + i * 256;
        int row = idx >> 3, qc = idx & 7;
        uint32_t soff = (uint32_t)(row * SROW + qc * 4) * 4;
        cp_async16(sb + soff, A + (size_t)(m0 + row) * lda + qc * 8);
        cp_async16(sb + (uint32_t)(2 * STG_W) * 4 + soff,
                   Bt + (size_t)(n0 + row) * kdim + qc * 8);
    }
    cp_commit();

    for (int c = 0; c < nch; c++) {
        int p = c & 1;
        if (c + 1 < nch) {
            int pn = (c + 1) & 1;
            uint32_t asn = sb + (uint32_t)(pn * STG_W) * 4;
            uint32_t bsn = asn + (uint32_t)(2 * STG_W) * 4;
            const __half* An = A + (c + 1) * KCH;
            const __half* Bn = Bt + (c + 1) * KCH;
#pragma unroll
            for (int i = 0; i < 4; i++) {
                int idx = tid + i * 256;
                int row = idx >> 3, qc = idx & 7;
                uint32_t soff = (uint32_t)(row * SROW + qc * 4) * 4;
                cp_async16(asn + soff, An + (size_t)(m0 + row) * lda + qc * 8);
                cp_async16(bsn + soff, Bn + (size_t)(n0 + row) * kdim + qc * 8);
            }
            cp_commit();
            asm volatile("cp.async.wait_group 1;");
        } else {
            asm volatile("cp.async.wait_group 0;");
        }
        __syncthreads();

        uint32_t abase = sb + (uint32_t)(p * STG_W) * 4;
        uint32_t bbase = abase + (uint32_t)(2 * STG_W) * 4;
#pragma unroll
        for (int kk = 0; kk < 4; kk++) {
            uint32_t kadd = (uint32_t)(kk * 32);
            uint32_t a[4][4], b[4][2];
#pragma unroll
            for (int mt = 0; mt < 4; mt++)
                LDSM4(a[mt][0], a[mt][1], a[mt][2], a[mt][3], abase + aoff[mt] + kadd);
            LDSM4(b[0][0], b[0][1], b[1][0], b[1][1], bbase + boff[0] + kadd);
            LDSM4(b[2][0], b[2][1], b[3][0], b[3][1], bbase + boff[1] + kadd);
#pragma unroll
            for (int mt = 0; mt < 4; mt++)
#pragma unroll
                for (int nt = 0; nt < 4; nt++)
                    mma_f16_16n8k16(acc[mt][nt], a[mt], b[nt]);
        }
        __syncthreads();
    }

    // fused epilogue
#pragma unroll
    for (int mt = 0; mt < 4; mt++) {
#pragma unroll
        for (int half_ = 0; half_ < 2; half_++) {
            int grow = m0 + wm + 16 * mt + gid + 8 * half_;
#pragma unroll
            for (int nt = 0; nt < 4; nt++) {
                int gcol = n0 + wn + 8 * nt + 2 * tig;
                float v0 = acc[mt][nt][half_ * 2 + 0];
                float v1 = acc[mt][nt][half_ * 2 + 1];
                if (MODE == 0) {
                    int z = gcol >> 10, rem = gcol & 1023, h = rem >> 6, kk = rem & 63;
                    int b = grow >> 11, t = grow & 2047;
                    __half* dst = &g_qkv[z][(((size_t)(b * CH + h) * CT) + t) * CK + kk];
                    *(__half2*)dst = __floats2half2_rn(v0, v1);
                } else if (MODE == 1 || MODE == 3) {
                    const float* xr = &xres[(size_t)grow * ldout + gcol];
                    float* dst = &out[(size_t)grow * ldout + gcol];
                    dst[0] = xr[0] + v0 + bias[gcol];
                    dst[1] = xr[1] + v1 + bias[gcol + 1];
                } else {
                    float u0 = v0 + bias[gcol];
                    float u1 = v1 + bias[gcol + 1];
                    float r0 = 0.5f * u0 * (1.f + erff(u0 * 0.70710678118654752f));
                    float r1 = 0.5f * u1 * (1.f + erff(u1 * 0.70710678118654752f));
                    __half* oh = (__half*)out;
                    *(__half2*)&oh[(size_t)grow * ldout + gcol] =
                        __floats2half2_rn(r0, r1);
                }
            }
        }
    }
}

// ================ Flash attention on mma.sync fp16 =================
// R14 structure (single-buffer smem, 2 syncs/kb) with two changes:
//  - V stored NATURALLY ([key][d], uint4 copy); PV B-operand read via
//    ldmatrix.x4.trans (layout verified bit-exact in R15)
//  - qi reversed so longest-causal CTAs launch first
#define AROW 72                              // halves per row
#define RB 144                               // bytes per row
#define ATTN_SMEM_BYTES (3 * 64 * AROW * 2)  // 27648

__global__ void __launch_bounds__(128) k_attn_mma() {
    extern __shared__ __half smh[];
    __half* Ksh = smh;                // [64][AROW]  (keys natural)
    __half* Vsh = smh + 64 * AROW;    // [64][AROW]  (V natural)
    __half* Psh = smh + 2 * 64 * AROW;// [64][AROW]  (Q staging / P tiles)

    int tid = threadIdx.x, wid = tid >> 5, lane = tid & 31;
    int gid = lane >> 2, tig = lane & 3;
    int qi = gridDim.x - 1 - blockIdx.x;   // longest CTAs first
    int bh = blockIdx.y;
    int q0 = qi * 64;

    uint32_t ksb = smem_u32(Ksh);
    uint32_t vsb = smem_u32(Vsh);
    uint32_t psb = smem_u32(Psh);

    const __half* Q  = g_qkv[0] + (size_t)bh * CT * CK;
    const __half* Kp = g_qkv[1] + (size_t)bh * CT * CK;
    const __half* Vp = g_qkv[2] + (size_t)bh * CT * CK;

    // ldmatrix per-lane offsets
    int l8 = lane & 7, b3 = (lane >> 3) & 1, b4 = lane >> 4;
    uint32_t aoffP = (uint32_t)((wid * 16 + l8 + 8 * b3) * RB) + 16u * b4;
    uint32_t boffK[4];
#pragma unroll
    for (int j = 0; j < 4; j++)
        boffK[j] = (uint32_t)((8 * (2 * j + b4) + l8) * RB) + 16u * b3;
    // V trans offsets: row = key (8*b3 + l8), 16B col = d-block (2j + b4)
    uint32_t boffV[4];
#pragma unroll
    for (int j = 0; j < 4; j++)
        boffV[j] = (uint32_t)((8 * b3 + l8) * RB) + (uint32_t)(2 * j + b4) * 16u;

    // stage Q (scaled by 1/8) into Ps
    const __half2 qscale = __float2half2_rn(0.125f);
#pragma unroll
    for (int i = 0; i < 4; i++) {
        int idx = tid + i * 128;
        int r = idx >> 3, qc = idx & 7;
        uint4 v = *(const uint4*)(Q + (size_t)(q0 + r) * CK + qc * 8);
        __half2* h = (__half2*)&v;
        h[0] = __hmul2(h[0], qscale); h[1] = __hmul2(h[1], qscale);
        h[2] = __hmul2(h[2], qscale); h[3] = __hmul2(h[3], qscale);
        *(uint4*)&Psh[r * AROW + qc * 8] = v;
    }
    __syncthreads();

    int rA = wid * 16 + gid;           // warp row A; row B = rA + 8
    uint32_t qf[4][4];
#pragma unroll
    for (int kk = 0; kk < 4; kk++)
        LDSM4(qf[kk][0], qf[kk][1], qf[kk][2], qf[kk][3],
              psb + aoffP + (uint32_t)(kk * 32));

    float oacc[8][4];
#pragma unroll
    for (int nt = 0; nt < 8; nt++)
#pragma unroll
        for (int q = 0; q < 4; q++) oacc[nt][q] = 0.f;
    float mA = -INFINITY, mB = -INFINITY, lA = 0.f, lB = 0.f;

    int grA = q0 + rA, grB = grA + 8;
    const int nkb = qi + 1;

    for (int kb = 0; kb < nkb; kb++) {
        __syncthreads();   // protect tile reuse
        // K and V: straight uint4 copies (natural [key][d])
#pragma unroll
        for (int i = 0; i < 4; i++) {
            int idx = tid + i * 128;
            int n = idx >> 3, qc = idx & 7;
            uint4 kv = *(const uint4*)(Kp + (size_t)(kb * 64 + n) * CK + qc * 8);
            *(uint4*)&Ksh[n * AROW + qc * 8] = kv;
            uint4 vv = *(const uint4*)(Vp + (size_t)(kb * 64 + n) * CK + qc * 8);
            *(uint4*)&Vsh[n * AROW + qc * 8] = vv;
        }
        __syncthreads();

        // S = Q K^T  (warp: 16 x 64), fp16 mma + LDSM
        float sacc[8][4];
#pragma unroll
        for (int nt = 0; nt < 8; nt++)
#pragma unroll
            for (int q = 0; q < 4; q++) sacc[nt][q] = 0.f;
#pragma unroll
        for (int kk = 0; kk < 4; kk++) {
            uint32_t kadd = (uint32_t)(kk * 32);
#pragma unroll
            for (int j = 0; j < 4; j++) {
                uint32_t bb[4];
                LDSM4(bb[0], bb[1], bb[2], bb[3], ksb + boffK[j] + kadd);
                mma_f16_16n8k16(sacc[2 * j], qf[kk], bb);
                mma_f16_16n8k16(sacc[2 * j + 1], qf[kk], bb + 2);
            }
        }

        // causal mask (register)
        if (kb * 64 + 63 > q0 + wid * 16) {
#pragma unroll
            for (int nt = 0; nt < 8; nt++) {
                int c0 = kb * 64 + 8 * nt + 2 * tig;
                if (c0     > grA) sacc[nt][0] = -INFINITY;
                if (c0 + 1 > grA) sacc[nt][1] = -INFINITY;
                if (c0     > grB) sacc[nt][2] = -INFINITY;
                if (c0 + 1 > grB) sacc[nt][3] = -INFINITY;
            }
        }

        // online softmax (fp32 registers)
        float mxA = -INFINITY, mxB = -INFINITY;
#pragma unroll
        for (int nt = 0; nt < 8; nt++) {
            mxA = fmaxf(mxA, fmaxf(sacc[nt][0], sacc[nt][1]));
            mxB = fmaxf(mxB, fmaxf(sacc[nt][2], sacc[nt][3]));
        }
        mxA = fmaxf(mxA, __shfl_xor_sync(0xffffffffu, mxA, 1));
        mxA = fmaxf(mxA, __shfl_xor_sync(0xffffffffu, mxA, 2));
        mxB = fmaxf(mxB, __shfl_xor_sync(0xffffffffu, mxB, 1));
        mxB = fmaxf(mxB, __shfl_xor_sync(0xffffffffu, mxB, 2));
        float mnA = fmaxf(mA, mxA), mnB = fmaxf(mB, mxB);
        float aA = __expf(mA - mnA), aB = __expf(mB - mnB);
        lA *= aA; lB *= aB;
        __half* prA = &Psh[rA * AROW];
        __half* prB = prA + 8 * AROW;
#pragma unroll
        for (int nt = 0; nt < 8; nt++) {
            float p0 = __expf(sacc[nt][0] - mnA);
            float p1 = __expf(sacc[nt][1] - mnA);
            float p2 = __expf(sacc[nt][2] - mnB);
            float p3 = __expf(sacc[nt][3] - mnB);
            lA += p0 + p1; lB += p2 + p3;
            int c = 8 * nt + 2 * tig;
            *(__half2*)&prA[c] = __floats2half2_rn(p0, p1);
            *(__half2*)&prB[c] = __floats2half2_rn(p2, p3);
            oacc[nt][0] *= aA; oacc[nt][1] *= aA;
            oacc[nt][2] *= aB; oacc[nt][3] *= aB;
        }
        mA = mnA; mB = mnB;
        __syncwarp();

        // O += P V  (A = own-warp P rows via LDSM, B = natural V via LDSM.trans)
#pragma unroll
        for (int kk = 0; kk < 4; kk++) {
            uint32_t pa[4];
            LDSM4(pa[0], pa[1], pa[2], pa[3], psb + aoffP + (uint32_t)(kk * 32));
            uint32_t vkadd = (uint32_t)(kk * 16 * RB);   // advance 16 keys
#pragma unroll
            for (int j = 0; j < 4; j++) {
                uint32_t bb[4];
                LDSM4T(bb[0], bb[1], bb[2], bb[3], vsb + boffV[j] + vkadd);
                mma_f16_16n8k16(oacc[2 * j], pa, bb);
                mma_f16_16n8k16(oacc[2 * j + 1], pa, bb + 2);
            }
        }
        __syncwarp();
    }

    lA += __shfl_xor_sync(0xffffffffu, lA, 1);
    lA += __shfl_xor_sync(0xffffffffu, lA, 2);
    lB += __shfl_xor_sync(0xffffffffu, lB, 1);
    lB += __shfl_xor_sync(0xffffffffu, lB, 2);
    float iA = 1.f / lA, iB = 1.f / lB;

    // write concat output (fp16, feeds Wo GEMM as A operand)
    int b = bh >> 4, h = bh & 15;
    size_t baseA = ((size_t)(b * CT + grA)) * CD + h * 64;
    size_t baseB = ((size_t)(b * CT + grB)) * CD + h * 64;
#pragma unroll
    for (int nt = 0; nt < 8; nt++) {
        int c = 8 * nt + 2 * tig;
        *(__half2*)&g_oc[baseA + c] = __floats2half2_rn(oacc[nt][0] * iA, oacc[nt][1] * iA);
        *(__half2*)&g_oc[baseB + c] = __floats2half2_rn(oacc[nt][2] * iB, oacc[nt][3] * iB);
    }
}

// ============================= launch ==============================
extern "C" void kernel_launch(void* const* d_in, const int* in_sizes, int n_in,
                              void* d_out, int out_size) {
    (void)in_sizes; (void)n_in; (void)out_size;
    const float* x   = (const float*)d_in[0];
    const float* Wq  = (const float*)d_in[1];
    const float* Wk  = (const float*)d_in[2];
    const float* Wv  = (const float*)d_in[3];
    const float* Wo  = (const float*)d_in[4];
    const float* bo  = (const float*)d_in[5];
    const float* W1  = (const float*)d_in[6];
    const float* b1  = (const float*)d_in[7];
    const float* W2  = (const float*)d_in[8];
    const float* b2  = (const float*)d_in[9];
    const float* g1  = (const float*)d_in[10];
    const float* be1 = (const float*)d_in[11];
    const float* g2  = (const float*)d_in[12];
    const float* be2 = (const float*)d_in[13];
    float* out = (float*)d_out;

    cudaFuncSetAttribute(k_attn_mma, cudaFuncAttributeMaxDynamicSharedMemorySize, ATTN_SMEM_BYTES);
    cudaFuncSetAttribute(k_gemm<0>, cudaFuncAttributeMaxDynamicSharedMemorySize, GEMM_SMEM);
    cudaFuncSetAttribute(k_gemm<1>, cudaFuncAttributeMaxDynamicSharedMemorySize, GEMM_SMEM);
    cudaFuncSetAttribute(k_gemm<2>, cudaFuncAttributeMaxDynamicSharedMemorySize, GEMM_SMEM);
    cudaFuncSetAttribute(k_gemm<3>, cudaFuncAttributeMaxDynamicSharedMemorySize, GEMM_SMEM);

    __half* g_qkvwt_p; cudaGetSymbolAddress((void**)&g_qkvwt_p, g_qkvwt);
    __half* g_wot_p;   cudaGetSymbolAddress((void**)&g_wot_p, g_wot);
    __half* g_w1t_p;   cudaGetSymbolAddress((void**)&g_w1t_p, g_w1t);
    __half* g_w2t_p;   cudaGetSymbolAddress((void**)&g_w2t_p, g_w2t);
    __half* g_h1_p;    cudaGetSymbolAddress((void**)&g_h1_p, g_h1);
    __half* g_oc_p;    cudaGetSymbolAddress((void**)&g_oc_p, g_oc);
    float*  g_x2_p;    cudaGetSymbolAddress((void**)&g_x2_p, g_x2);
    __half* g_h2_p;    cudaGetSymbolAddress((void**)&g_h2_p, g_h2);
    __half* g_ff_p;    cudaGetSymbolAddress((void**)&g_ff_p, g_ff);

    // weight transposes -> [N][K] fp16
    k_qkvw_tr<<<dim3(CK / 32, CD / 32, 48), dim3(32, 8)>>>(Wq, Wk, Wv);
    k_tr<<<dim3(CD / 32, CD / 32), dim3(32, 8)>>>(Wo, g_wot_p, CD, CD);
    k_tr<<<dim3(CDFF / 32, CD / 32), dim3(32, 8)>>>(W1, g_w1t_p, CD, CDFF);
    k_tr<<<dim3(CD / 32, CDFF / 32), dim3(32, 8)>>>(W2, g_w2t_p, CDFF, CD);

    k_ln1<<<CBT, 256>>>(x, g1, be1);
    // QKV: [4096 x 3072]
    k_gemm<0><<<dim3(CBT / 128, 3 * CD / 128), 256, GEMM_SMEM>>>(
        g_h1_p, CD, g_qkvwt_p, CD, nullptr, nullptr, nullptr, 0);
    k_attn_mma<<<dim3(CT / 64, CB * CH), 128, ATTN_SMEM_BYTES>>>();
    // Wo + residual
    k_gemm<1><<<dim3(CBT / 128, CD / 128), 256, GEMM_SMEM>>>(
        g_oc_p, CD, g_wot_p, CD, bo, x, g_x2_p, CD);
    k_ln2<<<CBT, 256>>>(g2, be2);
    // FF1 + gelu -> fp16 g_ff
    k_gemm<2><<<dim3(CBT / 128, CDFF / 128), 256, GEMM_SMEM>>>(
        g_h2_p, CD, g_w1t_p, CD, b1, nullptr, (float*)g_ff_p, CDFF);
    // FF2 + residual -> out
    k_gemm<3><<<dim3(CBT / 128, CD / 128), 256, GEMM_SMEM>>>(
        g_ff_p, CDFF, g_w2t_p, CDFF, b2, g_x2_p, out, CD);
}